// round 11
// baseline (speedup 1.0000x reference)
#include <cuda_runtime.h>
#include <cstdint>

#define NTHR 256
#define TOKB 64                  // tokens per CTA
#define EXPN 64
#define CDIM 2048
#define BT   16384
#define BDIM 4
#define TOPK 6
#define NK32 64                  // kstep32 count = 2048/32
#define CHK  4                   // kstep32 per chunk
#define NCHK (NK32/CHK)          // 16
#define CHUNK_U4 1024            // uint4 per chunk (4*8*32)
#define LSTR 66
#define TAU  1.0e-3f
#define SMEM_BYTES (2*CHUNK_U4*16 + TOKB*LSTR*4)   // 32768 + 16896 = 49664

#define S00 (1.52587890625e-05f)         // 2^-16  (x0*w0: 16*4096)
#define SXX (1.1920928955078125e-07f)    // 2^-23  (x1*w0 and x0*w1)
#define MAG 12582912.f                   // 1.5 * 2^23

__device__ float g_sums[BDIM * EXPN];
__device__ float g_cnts[BDIM * EXPN];
__device__ int   g_flagcnt;
__device__ int   g_flags[BT];
__device__ uint4 wsg4[NK32 * 8 * 32];    // 256 KB packed int8 W limb fragments

static __device__ __forceinline__ void cp16(void* smem_ptr, const void* gptr) {
    unsigned saddr = (unsigned)__cvta_generic_to_shared(smem_ptr);
    asm volatile("cp.async.cg.shared.global [%0], [%1], 16;\n" :: "r"(saddr), "l"(gptr));
}
#define CP_COMMIT() asm volatile("cp.async.commit_group;\n" ::: "memory")

static __device__ __forceinline__ void imma16832(int* c, const uint32_t* a,
                                                 uint32_t b0, uint32_t b1) {
    asm volatile("mma.sync.aligned.m16n8k32.row.col.s32.s8.s8.s32 "
        "{%0,%1,%2,%3}, {%4,%5,%6,%7}, {%8,%9}, {%0,%1,%2,%3};"
        : "+r"(c[0]), "+r"(c[1]), "+r"(c[2]), "+r"(c[3])
        : "r"(a[0]), "r"(a[1]), "r"(a[2]), "r"(a[3]), "r"(b0), "r"(b1));
}

static __device__ __forceinline__ uint32_t pack4(uint32_t a, uint32_t b,
                                                 uint32_t c, uint32_t d) {
    return __byte_perm(__byte_perm(a, b, 0x0040), __byte_perm(c, d, 0x0040), 0x5410);
}

// x quant: limb0 = round(x*16), limb1 = round((x - l0/16)*2048); all FP ops exact
static __device__ __forceinline__ void quantX4(float4 v, uint32_t& o0, uint32_t& o1) {
    float a0 = fmaf(v.x, 16.f, MAG), a1 = fmaf(v.y, 16.f, MAG);
    float a2 = fmaf(v.z, 16.f, MAG), a3 = fmaf(v.w, 16.f, MAG);
    float r0 = fmaf(a0 - MAG, -0.0625f, v.x), r1 = fmaf(a1 - MAG, -0.0625f, v.y);
    float r2 = fmaf(a2 - MAG, -0.0625f, v.z), r3 = fmaf(a3 - MAG, -0.0625f, v.w);
    float b0 = fmaf(r0, 2048.f, MAG), b1 = fmaf(r1, 2048.f, MAG);
    float b2 = fmaf(r2, 2048.f, MAG), b3 = fmaf(r3, 2048.f, MAG);
    o0 = pack4(__float_as_uint(a0), __float_as_uint(a1), __float_as_uint(a2), __float_as_uint(a3));
    o1 = pack4(__float_as_uint(b0), __float_as_uint(b1), __float_as_uint(b2), __float_as_uint(b3));
}

// w quant: limb0 = round(w*4096), limb1 = round((w - l0/4096)*2^19)
static __device__ __forceinline__ void quantW4(float4 v, uint32_t& o0, uint32_t& o1) {
    float a0 = fmaf(v.x, 4096.f, MAG), a1 = fmaf(v.y, 4096.f, MAG);
    float a2 = fmaf(v.z, 4096.f, MAG), a3 = fmaf(v.w, 4096.f, MAG);
    float r0 = fmaf(a0 - MAG, -0.000244140625f, v.x), r1 = fmaf(a1 - MAG, -0.000244140625f, v.y);
    float r2 = fmaf(a2 - MAG, -0.000244140625f, v.z), r3 = fmaf(a3 - MAG, -0.000244140625f, v.w);
    float b0 = fmaf(r0, 524288.f, MAG), b1 = fmaf(r1, 524288.f, MAG);
    float b2 = fmaf(r2, 524288.f, MAG), b3 = fmaf(r3, 524288.f, MAG);
    o0 = pack4(__float_as_uint(a0), __float_as_uint(a1), __float_as_uint(a2), __float_as_uint(a3));
    o1 = pack4(__float_as_uint(b0), __float_as_uint(b1), __float_as_uint(b2), __float_as_uint(b3));
}

// ---------------- W prep: int8 limb split packed in B-fragment lane order ----------------
__global__ void prep_kernel(const float* __restrict__ w) {
    int id = blockIdx.x * 256 + threadIdx.x;    // 16384 = 64 ksteps * 8 ntiles * 32 lanes
    if (id < BDIM * EXPN) { g_sums[id] = 0.f; g_cnts[id] = 0.f; }
    if (id == 0) g_flagcnt = 0;
    int s = id >> 8;
    int j = (id >> 5) & 7;
    int l = id & 31;
    int n  = 8 * j + (l >> 2);
    int k0 = 32 * s + (l & 3) * 4;
    const float* wr = w + (size_t)n * CDIM + k0;
    float4 lo = *(const float4*)wr;
    float4 hi = *(const float4*)(wr + 16);
    uint32_t w0lo, w1lo, w0hi, w1hi;
    quantW4(lo, w0lo, w1lo);
    quantW4(hi, w0hi, w1hi);
    wsg4[id] = make_uint4(w0lo, w0hi, w1lo, w1hi);
}

// ---------------- main gate kernel ----------------
__global__ void __launch_bounds__(NTHR, 2)
gate_kernel(const float* __restrict__ x, float* __restrict__ out) {
    extern __shared__ char smem[];
    uint4* wbuf = (uint4*)smem;                       // 2 x 16KB chunk buffers
    float* lsm = (float*)(smem + 2 * CHUNK_U4 * 16);  // 64 x 66 logits
    __shared__ float s_sums[EXPN];
    __shared__ float s_cnt[EXPN];

    const int tid  = threadIdx.x;
    const int wid  = tid >> 5;
    const int lane = tid & 31;
    const int blk  = blockIdx.x;
    const int mt   = wid & 3;    // m-tile (16 tokens)
    const int nh   = wid >> 2;   // ntile half

    if (tid < EXPN) { s_sums[tid] = 0.f; s_cnt[tid] = 0.f; }

    const int r  = lane >> 2;
    const int c4 = lane & 3;
    const float* xr = x + ((size_t)blk * TOKB + mt * 16 + r) * CDIM + c4 * 4;

    int acc00[4][4], acc01[4][4], acc10[4][4];
#pragma unroll
    for (int j = 0; j < 4; j++)
#pragma unroll
        for (int q = 0; q < 4; q++) { acc00[j][q] = 0; acc01[j][q] = 0; acc10[j][q] = 0; }

    auto load1 = [&](int c) {
        const uint4* s0 = wsg4 + (size_t)c * CHUNK_U4;
        uint4* d0 = wbuf + (c & 1) * CHUNK_U4;
#pragma unroll
        for (int i = 0; i < 4; i++) cp16(d0 + tid + i * NTHR, s0 + tid + i * NTHR);
        CP_COMMIT();
    };

    load1(0);
    load1(1);

    for (int c = 0; c < NCHK; c++) {
        if (c + 1 < NCHK) asm volatile("cp.async.wait_group 1;\n" ::: "memory");
        else              asm volatile("cp.async.wait_group 0;\n" ::: "memory");
        __syncthreads();

        const uint4* wb = wbuf + (c & 1) * CHUNK_U4;

#pragma unroll
        for (int kc = 0; kc < CHK; kc++) {
            const int ks = c * CHK + kc;
            const float4* p0 = (const float4*)(xr + ks * 32);
            const float4* p1 = (const float4*)(xr + ks * 32 + 8 * CDIM);
            float4 xv0 = p0[0];
            float4 xv2 = p0[4];
            float4 xv1 = p1[0];
            float4 xv3 = p1[4];

            uint32_t A0[4], A1[4];
            quantX4(xv0, A0[0], A1[0]);
            quantX4(xv1, A0[1], A1[1]);
            quantX4(xv2, A0[2], A1[2]);
            quantX4(xv3, A0[3], A1[3]);

            uint4 B[4];
#pragma unroll
            for (int jj = 0; jj < 4; jj++)
                B[jj] = wb[(kc * 8 + nh * 4 + jj) * 32 + lane];

#pragma unroll
            for (int jj = 0; jj < 4; jj++) imma16832(acc00[jj], A0, B[jj].x, B[jj].y);
#pragma unroll
            for (int jj = 0; jj < 4; jj++) imma16832(acc10[jj], A1, B[jj].x, B[jj].y);
#pragma unroll
            for (int jj = 0; jj < 4; jj++) imma16832(acc01[jj], A0, B[jj].z, B[jj].w);
        }
        __syncthreads();
        if (c + 2 < NCHK) load1(c + 2);
    }

    // ---- reconstruct fp32 logits -> smem ----
    // logit = acc00*2^-16 + (acc10 + acc01)*2^-23   (both cross terms scale 2^-23)
    {
        const int row0 = mt * 16 + r;
#pragma unroll
        for (int jj = 0; jj < 4; jj++) {
            int nb = 8 * (nh * 4 + jj) + c4 * 2;
            float l0 = fmaf((float)acc00[jj][0], S00, (float)(acc10[jj][0] + acc01[jj][0]) * SXX);
            float l1 = fmaf((float)acc00[jj][1], S00, (float)(acc10[jj][1] + acc01[jj][1]) * SXX);
            float l2 = fmaf((float)acc00[jj][2], S00, (float)(acc10[jj][2] + acc01[jj][2]) * SXX);
            float l3 = fmaf((float)acc00[jj][3], S00, (float)(acc10[jj][3] + acc01[jj][3]) * SXX);
            *(float2*)&lsm[row0 * LSTR + nb]       = make_float2(l0, l1);
            *(float2*)&lsm[(row0 + 8) * LSTR + nb] = make_float2(l2, l3);
        }
    }
    __syncthreads();

    // ---- per-token epilogue: top-7 tracking + flagging ----
    if (tid < TOKB) {
        float* row = lsm + tid * LSTR;

        float v0 = -1e38f, v1 = -1e38f, v2 = -1e38f, v3 = -1e38f, v4 = -1e38f, v5 = -1e38f, v6 = -1e38f;
        int   i0 = 0, i1 = 0, i2 = 0, i3 = 0, i4 = 0, i5 = 0;
        for (int e = 0; e < EXPN; e++) {
            float l = row[e];
            if (l > v6) {
                v6 = l;
                int ie = e;
                if (v6 > v5) { float t = v5; v5 = v6; v6 = t; int u = i5; i5 = ie; ie = u;
                if (v5 > v4) { t = v4; v4 = v5; v5 = t; u = i4; i4 = i5; i5 = u;
                if (v4 > v3) { t = v3; v3 = v4; v4 = t; u = i3; i3 = i4; i4 = u;
                if (v3 > v2) { t = v2; v2 = v3; v3 = t; u = i2; i2 = i3; i3 = u;
                if (v2 > v1) { t = v1; v1 = v2; v2 = t; u = i1; i1 = i2; i2 = u;
                if (v1 > v0) { t = v0; v0 = v1; v1 = t; u = i0; i0 = i1; i1 = u; } } } } } }
            }
        }

        float mg = v0 - v1;
        mg = fminf(mg, v1 - v2);
        mg = fminf(mg, v2 - v3);
        mg = fminf(mg, v3 - v4);
        mg = fminf(mg, v4 - v5);
        mg = fminf(mg, v5 - v6);
        const int tok = blk * TOKB + tid;
        if (mg < TAU) {
            int slot = atomicAdd(&g_flagcnt, 1);
            g_flags[slot] = tok;
        }

        float m = v0;
        float ssum = 0.f;
        for (int e = 0; e < EXPN; e++) {
            float p = expf(row[e] - m);
            ssum += p;
            row[e] = p;
        }
        float inv = 1.0f / ssum;

        const size_t g = (size_t)tok;
        float* out_idx = out;
        float* out_wgt = out + (size_t)BT * TOPK;

        out_idx[g * TOPK + 0] = (float)i0;
        out_idx[g * TOPK + 1] = (float)i1;
        out_idx[g * TOPK + 2] = (float)i2;
        out_idx[g * TOPK + 3] = (float)i3;
        out_idx[g * TOPK + 4] = (float)i4;
        out_idx[g * TOPK + 5] = (float)i5;

        out_wgt[g * TOPK + 0] = row[i0] * inv;
        out_wgt[g * TOPK + 1] = row[i1] * inv;
        out_wgt[g * TOPK + 2] = row[i2] * inv;
        out_wgt[g * TOPK + 3] = row[i3] * inv;
        out_wgt[g * TOPK + 4] = row[i4] * inv;
        out_wgt[g * TOPK + 5] = row[i5] * inv;

        for (int jj = 0; jj < EXPN; jj++) {
            int e = (tid + jj) & (EXPN - 1);
            atomicAdd(&s_sums[e], row[e] * inv);
        }
        atomicAdd(&s_cnt[i0], 1.0f);
        atomicAdd(&s_cnt[i1], 1.0f);
        atomicAdd(&s_cnt[i2], 1.0f);
        atomicAdd(&s_cnt[i3], 1.0f);
        atomicAdd(&s_cnt[i4], 1.0f);
        atomicAdd(&s_cnt[i5], 1.0f);
    }
    __syncthreads();

    if (tid < EXPN) {
        int b = blk >> 6;   // 64 CTAs (4096 tokens) per batch element
        atomicAdd(&g_sums[b * EXPN + tid], s_sums[tid]);
        atomicAdd(&g_cnts[b * EXPN + tid], s_cnt[tid]);
    }
}

// ---------------- fixup: bit-exact R1 fp32 order + merged aux ----------------
__global__ void __launch_bounds__(256, 1)
fixup_kernel(const float* __restrict__ x, const float* __restrict__ w,
             float* __restrict__ out) {
    __shared__ float ws[EXPN * 129];
    __shared__ float lg[4][EXPN];
    __shared__ float red[256];
    const int tid = threadIdx.x;
    const int tg  = tid >> 6;
    const int e   = tid & 63;
    const int nflag = g_flagcnt;

    for (int base = blockIdx.x * 4; base < nflag; base += gridDim.x * 4) {
        const int fi  = base + tg;
        const int tok = g_flags[fi < nflag ? fi : (nflag - 1)];

        float accE = 0.f, accO = 0.f;
        for (int ch = 0; ch < 16; ch++) {
            __syncthreads();
            for (int i = tid; i < EXPN * 32; i += 256) {
                int row = i >> 5;
                int q4  = i & 31;
                float4 v = *(const float4*)(w + (size_t)row * CDIM + ch * 128 + q4 * 4);
                float* d = &ws[row * 129 + q4 * 4];
                d[0] = v.x; d[1] = v.y; d[2] = v.z; d[3] = v.w;
            }
            __syncthreads();
            const float* xp = x + (size_t)tok * CDIM + ch * 128;
            const float* wr = &ws[e * 129];
#pragma unroll 8
            for (int kk = 0; kk < 128; kk += 2) {
                float2 xv = *(const float2*)(xp + kk);
                accE = fmaf(xv.x, wr[kk],     accE);
                accO = fmaf(xv.y, wr[kk + 1], accO);
            }
        }
        lg[tg][e] = accE + accO;
        __syncthreads();

        if (tid < 4 && base + tid < nflag) {
            const int t2 = g_flags[base + tid];
            const float* row = lg[tid];
            float v0 = -1e38f, v1 = -1e38f, v2 = -1e38f, v3 = -1e38f, v4 = -1e38f, v5 = -1e38f;
            int   i0 = 0, i1 = 0, i2 = 0, i3 = 0, i4 = 0, i5 = 0;
            for (int k = 0; k < EXPN; k++) {
                float l = row[k];
                if (l > v5) {
                    v5 = l; i5 = k;
                    if (v5 > v4) { float t = v4; v4 = v5; v5 = t; int u = i4; i4 = i5; i5 = u; }
                    if (v4 > v3) { float t = v3; v3 = v4; v4 = t; int u = i3; i3 = i4; i4 = u; }
                    if (v3 > v2) { float t = v2; v2 = v3; v3 = t; int u = i2; i2 = i3; i3 = u; }
                    if (v2 > v1) { float t = v1; v1 = v2; v2 = t; int u = i1; i1 = i2; i2 = u; }
                    if (v1 > v0) { float t = v0; v0 = v1; v1 = t; int u = i0; i0 = i1; i1 = u; }
                }
            }
            float m = v0;
            float ssum = 0.f;
            for (int k = 0; k < EXPN; k++) ssum += expf(row[k] - m);
            float inv = 1.0f / ssum;

            float* out_idx = out;
            float* out_wgt = out + (size_t)BT * TOPK;
            const size_t g = (size_t)t2;
            out_idx[g * TOPK + 0] = (float)i0;
            out_idx[g * TOPK + 1] = (float)i1;
            out_idx[g * TOPK + 2] = (float)i2;
            out_idx[g * TOPK + 3] = (float)i3;
            out_idx[g * TOPK + 4] = (float)i4;
            out_idx[g * TOPK + 5] = (float)i5;
            out_wgt[g * TOPK + 0] = expf(v0 - m) * inv;
            out_wgt[g * TOPK + 1] = expf(v1 - m) * inv;
            out_wgt[g * TOPK + 2] = expf(v2 - m) * inv;
            out_wgt[g * TOPK + 3] = expf(v3 - m) * inv;
            out_wgt[g * TOPK + 4] = expf(v4 - m) * inv;
            out_wgt[g * TOPK + 5] = expf(v5 - m) * inv;
        }
        __syncthreads();
    }

    // merged aux loss (block 0)
    if (blockIdx.x == 0) {
        red[tid] = g_cnts[tid] * g_sums[tid];
        __syncthreads();
#pragma unroll
        for (int s = 128; s > 0; s >>= 1) {
            if (tid < s) red[tid] += red[tid + s];
            __syncthreads();
        }
        if (tid == 0) {
            const float scale = (float)(0.001 * 64.0 / ((double)4 * 4096.0 * 6.0 * 4096.0));
            out[(size_t)BT * 12] = red[0] * scale;
        }
    }
}

extern "C" void kernel_launch(void* const* d_in, const int* in_sizes, int n_in,
                              void* d_out, int out_size) {
    const float* x = (const float*)d_in[0];
    const float* w = (const float*)d_in[1];
    float* out = (float*)d_out;

    cudaFuncSetAttribute(gate_kernel, cudaFuncAttributeMaxDynamicSharedMemorySize, SMEM_BYTES);

    prep_kernel<<<64, 256>>>(w);
    gate_kernel<<<BT / TOKB, NTHR, SMEM_BYTES>>>(x, out);
    fixup_kernel<<<128, 256>>>(x, w, out);
}

// round 12
// speedup vs baseline: 1.5685x; 1.5685x over previous
#include <cuda_runtime.h>
#include <cuda_bf16.h>
#include <cstdint>

#define NTHR 384
#define TOKB 128
#define EXPN 64
#define CDIM 2048
#define BT   16384
#define BDIM 4
#define TOPK 6
#define LSTR 66
#define TAU  1.0e-4f

// smem layout (bytes)
#define OFF_WBUF 0
#define WBUF_PAR 16384           // 4096 u32 per parity
#define OFF_FX   32768
#define FX_PAR   17408           // 64 rows * 68 floats * 4B
#define OFF_FW   67584
#define FW_PAR   17408
#define OFF_LSM  32768           // aliases fx (used only after mainloop)
#define SMEM_BYTES 102400

__device__ float g_sums[BDIM * EXPN];
__device__ float g_cnts[BDIM * EXPN];
__device__ int   g_flagcnt;
__device__ int   g_flags[BT];
__device__ uint32_t wsg[128 * 1024];   // 512 KB packed 2-plane bf16 W fragments

static __device__ __forceinline__ void cp16(void* smem_ptr, const void* gptr) {
    unsigned saddr = (unsigned)__cvta_generic_to_shared(smem_ptr);
    asm volatile("cp.async.cg.shared.global [%0], [%1], 16;\n" :: "r"(saddr), "l"(gptr));
}
#define CP_COMMIT() asm volatile("cp.async.commit_group;\n" ::: "memory")

static __device__ __forceinline__ void mma16816(float* c, const uint32_t* a,
                                                uint32_t b0, uint32_t b1) {
    asm volatile("mma.sync.aligned.m16n8k16.row.col.f32.bf16.bf16.f32 "
        "{%0,%1,%2,%3}, {%4,%5,%6,%7}, {%8,%9}, {%0,%1,%2,%3};"
        : "+f"(c[0]), "+f"(c[1]), "+f"(c[2]), "+f"(c[3])
        : "r"(a[0]), "r"(a[1]), "r"(a[2]), "r"(a[3]), "r"(b0), "r"(b1));
}

static __device__ __forceinline__ void split2(float f0, float f1,
                                              uint32_t& o0, uint32_t& o1) {
    __nv_bfloat162 b = __floats2bfloat162_rn(f0, f1);
    uint32_t u = *(uint32_t*)&b;
    o0 = u;
    float g0 = __int_as_float(u << 16);
    float g1 = __int_as_float(u & 0xffff0000u);
    __nv_bfloat162 c = __floats2bfloat162_rn(f0 - g0, f1 - g1);
    o1 = *(uint32_t*)&c;
}

static __device__ __forceinline__ unsigned long long pk(float a, float b) {
    unsigned long long r;
    asm("mov.b64 %0, {%1, %2};" : "=l"(r) : "f"(a), "f"(b));
    return r;
}
static __device__ __forceinline__ void ffma2(unsigned long long& d, unsigned long long a, unsigned long long b) {
    asm("fma.rn.f32x2 %0, %1, %2, %0;" : "+l"(d) : "l"(a), "l"(b));
}
static __device__ __forceinline__ void unpk(unsigned long long v, float& lo, float& hi) {
    asm("mov.b64 {%0, %1}, %2;" : "=f"(lo), "=f"(hi) : "l"(v));
}

// ---------------- W prep: bf16 2-plane split packed in B-fragment lane order ----------------
__global__ void prep_kernel(const float* __restrict__ w) {
    int id = blockIdx.x * 256 + threadIdx.x;   // 32768 = 128 ksteps * 8 ntiles * 32 lanes
    if (id < BDIM * EXPN) { g_sums[id] = 0.f; g_cnts[id] = 0.f; }
    if (id == 0) g_flagcnt = 0;
    int s = id >> 8;
    int j = (id >> 5) & 7;
    int l = id & 31;
    int n  = 8 * j + (l >> 2);
    int k0 = s * 16 + (l & 3) * 2;
    const float* wr = w + (size_t)n * CDIM + k0;
    float2 flo = *(const float2*)wr;
    float2 fhi = *(const float2*)(wr + 8);
    uint32_t A, B, C, D;
    split2(flo.x, flo.y, A, B);
    split2(fhi.x, fhi.y, C, D);
    uint32_t base = (uint32_t)(((s * 4 + (j >> 1)) * 2 + (j & 1)) * 128 + l * 4);
    *(uint4*)&wsg[base] = make_uint4(A, C, B, D);
}

// ---------------- dual-engine gate kernel ----------------
__global__ void __launch_bounds__(NTHR, 1)
gate_kernel(const float* __restrict__ x, const float* __restrict__ w,
            float* __restrict__ out) {
    extern __shared__ char smem[];
    float* lsm = (float*)(smem + OFF_LSM);
    __shared__ float s_sums[EXPN];
    __shared__ float s_cnt[EXPN];

    const int tid  = threadIdx.x;
    const int wid  = tid >> 5;
    const int lane = tid & 31;
    const int blk  = blockIdx.x;

    if (tid < EXPN) { s_sums[tid] = 0.f; s_cnt[tid] = 0.f; }

    auto load2 = [&](int c) {
        int p = c & 1;
#pragma unroll
        for (int i = 0; i < 8; i++) {
            int u = tid + i * NTHR;   // 0..3071
            if (u < 1024) {
                cp16(smem + OFF_WBUF + p * WBUF_PAR + u * 16,
                     (const char*)wsg + (size_t)c * 16384 + u * 16);
            } else if (u < 2048) {
                int v = u - 1024, row = v >> 4, q = v & 15;
                cp16(smem + OFF_FX + p * FX_PAR + row * 272 + q * 16,
                     x + ((size_t)blk * TOKB + 64 + row) * CDIM + c * 64 + q * 4);
            } else {
                int v = u - 2048, row = v >> 4, q = v & 15;
                cp16(smem + OFF_FW + p * FW_PAR + row * 272 + q * 16,
                     w + (size_t)row * CDIM + c * 64 + q * 4);
            }
        }
        CP_COMMIT();
    };

    load2(0);
    load2(1);

    if (wid < 4) {
        // ================= HMMA engine: tokens 0..63, warp = one m-tile =================
        const int mt = wid;
        const int r  = lane >> 2;
        const int c0 = (lane & 3) * 2;
        const float* xr = x + ((size_t)blk * TOKB + mt * 16 + r) * CDIM;

        float cacc[8][4];
#pragma unroll
        for (int j = 0; j < 8; j++)
#pragma unroll
            for (int q = 0; q < 4; q++) cacc[j][q] = 0.f;

        float2 xf[2][4];
        auto ldx = [&](float2* d, int ks) {
            const float* p = xr + ks * 16 + c0;
            d[0] = *(const float2*)p;
            d[1] = *(const float2*)(p + 8 * CDIM);
            d[2] = *(const float2*)(p + 8);
            d[3] = *(const float2*)(p + 8 * CDIM + 8);
        };
        ldx(xf[0], 0);

        for (int c = 0; c < 32; c++) {
            if (c + 1 < 32) asm volatile("cp.async.wait_group 1;\n" ::: "memory");
            else            asm volatile("cp.async.wait_group 0;\n" ::: "memory");
            __syncthreads();

            const uint4* wk = (const uint4*)(smem + OFF_WBUF + (c & 1) * WBUF_PAR);

#pragma unroll
            for (int kc = 0; kc < 4; kc++) {
                const int ks = c * 4 + kc;
                const float2* xc = xf[kc & 1];
                if (ks + 1 < 128) ldx(xf[(kc & 1) ^ 1], ks + 1);

                uint32_t A0[4], A1[4];
                split2(xc[0].x, xc[0].y, A0[0], A1[0]);
                split2(xc[1].x, xc[1].y, A0[1], A1[1]);
                split2(xc[2].x, xc[2].y, A0[2], A1[2]);
                split2(xc[3].x, xc[3].y, A0[3], A1[3]);

#pragma unroll
                for (int jp = 0; jp < 4; jp++) {
                    uint4 G0 = wk[((kc * 4 + jp) * 2 + 0) * 32 + lane];
                    uint4 G1 = wk[((kc * 4 + jp) * 2 + 1) * 32 + lane];
                    float* e = cacc[2 * jp];
                    float* o = cacc[2 * jp + 1];
                    // per-acc order: x0*w0, x0*w1, x1*w0 (validated realization)
                    mma16816(e, A0, G0.x, G0.y);
                    mma16816(o, A0, G1.x, G1.y);
                    mma16816(e, A0, G0.z, G0.w);
                    mma16816(o, A0, G1.z, G1.w);
                    mma16816(e, A1, G0.x, G0.y);
                    mma16816(o, A1, G1.x, G1.y);
                }
            }
            __syncthreads();
            if (c + 2 < 32) load2(c + 2);
        }

        // write H logits (rows 0..63)
        const int row0 = mt * 16 + r;
#pragma unroll
        for (int j = 0; j < 8; j++) {
            int nb = 8 * j + c0;
            *(float2*)&lsm[row0 * LSTR + nb]       = make_float2(cacc[j][0], cacc[j][1]);
            *(float2*)&lsm[(row0 + 8) * LSTR + nb] = make_float2(cacc[j][2], cacc[j][3]);
        }
    } else {
        // ================= FFMA engine: tokens 64..127 (R1-exact realization) ============
        const int ftid  = tid - 128;      // 0..255
        const int tok_g = ftid >> 3;      // 0..31
        const int exp_g = ftid & 7;       // 0..7

        unsigned long long acc[2][8];
#pragma unroll
        for (int i = 0; i < 2; i++)
#pragma unroll
            for (int j = 0; j < 8; j++) acc[i][j] = 0ULL;

        for (int c = 0; c < 32; c++) {
            if (c + 1 < 32) asm volatile("cp.async.wait_group 1;\n" ::: "memory");
            else            asm volatile("cp.async.wait_group 0;\n" ::: "memory");
            __syncthreads();

            const float* fxp = (const float*)(smem + OFF_FX + (c & 1) * FX_PAR);
            const float* fwp = (const float*)(smem + OFF_FW + (c & 1) * FW_PAR);

#pragma unroll 4
            for (int k0 = 0; k0 < 16; k0++) {
                unsigned long long xa[2], xb[2], wa[8], wb[8];
#pragma unroll
                for (int i = 0; i < 2; i++) {
                    float4 v = *(const float4*)(fxp + (tok_g + 32 * i) * 68 + k0 * 4);
                    xa[i] = pk(v.x, v.y);
                    xb[i] = pk(v.z, v.w);
                }
#pragma unroll
                for (int j = 0; j < 8; j++) {
                    float4 v = *(const float4*)(fwp + (exp_g + 8 * j) * 68 + k0 * 4);
                    wa[j] = pk(v.x, v.y);
                    wb[j] = pk(v.z, v.w);
                }
#pragma unroll
                for (int i = 0; i < 2; i++)
#pragma unroll
                    for (int j = 0; j < 8; j++) {
                        ffma2(acc[i][j], xa[i], wa[j]);
                        ffma2(acc[i][j], xb[i], wb[j]);
                    }
            }
            __syncthreads();
            if (c + 2 < 32) load2(c + 2);
        }

        // write F logits (rows 64..127); defer until after H warps leave mainloop too
#pragma unroll
        for (int i = 0; i < 2; i++) {
            int row = 64 + tok_g + 32 * i;
#pragma unroll
            for (int j = 0; j < 8; j++) {
                float lo, hi;
                unpk(acc[i][j], lo, hi);
                lsm[row * LSTR + exp_g + 8 * j] = lo + hi;   // R1 even+odd chain sum
            }
        }
    }
    __syncthreads();

    // ---------------- per-token epilogue: top-7 + flagging + outputs + aux ----------------
    if (tid < TOKB) {
        float* row = lsm + tid * LSTR;

        float v0 = -1e38f, v1 = -1e38f, v2 = -1e38f, v3 = -1e38f, v4 = -1e38f, v5 = -1e38f, v6 = -1e38f;
        int   i0 = 0, i1 = 0, i2 = 0, i3 = 0, i4 = 0, i5 = 0;
        for (int e = 0; e < EXPN; e++) {
            float l = row[e];
            if (l > v6) {
                v6 = l;
                int ie = e;
                if (v6 > v5) { float t = v5; v5 = v6; v6 = t; int u = i5; i5 = ie; ie = u;
                if (v5 > v4) { t = v4; v4 = v5; v5 = t; u = i4; i4 = i5; i5 = u;
                if (v4 > v3) { t = v3; v3 = v4; v4 = t; u = i3; i3 = i4; i4 = u;
                if (v3 > v2) { t = v2; v2 = v3; v3 = t; u = i2; i2 = i3; i3 = u;
                if (v2 > v1) { t = v1; v1 = v2; v2 = t; u = i1; i1 = i2; i2 = u;
                if (v1 > v0) { t = v0; v0 = v1; v1 = t; u = i0; i0 = i1; i1 = u; } } } } } }
            }
        }

        float mg = v0 - v1;
        mg = fminf(mg, v1 - v2);
        mg = fminf(mg, v2 - v3);
        mg = fminf(mg, v3 - v4);
        mg = fminf(mg, v4 - v5);
        mg = fminf(mg, v5 - v6);
        const int tok = blk * TOKB + tid;
        if (mg < TAU) {
            int slot = atomicAdd(&g_flagcnt, 1);
            g_flags[slot] = tok;
        }

        float m = v0;
        float ssum = 0.f;
        for (int e = 0; e < EXPN; e++) {
            float p = expf(row[e] - m);
            ssum += p;
            row[e] = p;
        }
        float inv = 1.0f / ssum;

        const size_t g = (size_t)tok;
        float* out_idx = out;
        float* out_wgt = out + (size_t)BT * TOPK;

        out_idx[g * TOPK + 0] = (float)i0;
        out_idx[g * TOPK + 1] = (float)i1;
        out_idx[g * TOPK + 2] = (float)i2;
        out_idx[g * TOPK + 3] = (float)i3;
        out_idx[g * TOPK + 4] = (float)i4;
        out_idx[g * TOPK + 5] = (float)i5;

        out_wgt[g * TOPK + 0] = row[i0] * inv;
        out_wgt[g * TOPK + 1] = row[i1] * inv;
        out_wgt[g * TOPK + 2] = row[i2] * inv;
        out_wgt[g * TOPK + 3] = row[i3] * inv;
        out_wgt[g * TOPK + 4] = row[i4] * inv;
        out_wgt[g * TOPK + 5] = row[i5] * inv;

        for (int jj = 0; jj < EXPN; jj++) {
            int e = (tid + jj) & (EXPN - 1);
            atomicAdd(&s_sums[e], row[e] * inv);
        }
        atomicAdd(&s_cnt[i0], 1.0f);
        atomicAdd(&s_cnt[i1], 1.0f);
        atomicAdd(&s_cnt[i2], 1.0f);
        atomicAdd(&s_cnt[i3], 1.0f);
        atomicAdd(&s_cnt[i4], 1.0f);
        atomicAdd(&s_cnt[i5], 1.0f);
    }
    __syncthreads();

    if (tid < EXPN) {
        int b = blk >> 5;   // 32 CTAs (4096 tokens) per batch element
        atomicAdd(&g_sums[b * EXPN + tid], s_sums[tid]);
        atomicAdd(&g_cnts[b * EXPN + tid], s_cnt[tid]);
    }
}

// ---------------- fixup: bit-exact R1 fp32 order + merged aux ----------------
__global__ void __launch_bounds__(256, 1)
fixup_kernel(const float* __restrict__ x, const float* __restrict__ w,
             float* __restrict__ out) {
    __shared__ float ws[EXPN * 129];
    __shared__ float lg[4][EXPN];
    __shared__ float red[256];
    const int tid = threadIdx.x;
    const int tg  = tid >> 6;
    const int e   = tid & 63;
    const int nflag = g_flagcnt;

    for (int base = blockIdx.x * 4; base < nflag; base += gridDim.x * 4) {
        const int fi  = base + tg;
        const int tok = g_flags[fi < nflag ? fi : (nflag - 1)];

        float accE = 0.f, accO = 0.f;
        for (int ch = 0; ch < 16; ch++) {
            __syncthreads();
            for (int i = tid; i < EXPN * 32; i += 256) {
                int row = i >> 5;
                int q4  = i & 31;
                float4 v = *(const float4*)(w + (size_t)row * CDIM + ch * 128 + q4 * 4);
                float* d = &ws[row * 129 + q4 * 4];
                d[0] = v.x; d[1] = v.y; d[2] = v.z; d[3] = v.w;
            }
            __syncthreads();
            const float* xp = x + (size_t)tok * CDIM + ch * 128;
            const float* wr = &ws[e * 129];
#pragma unroll 8
            for (int kk = 0; kk < 128; kk += 2) {
                float2 xv = *(const float2*)(xp + kk);
                accE = fmaf(xv.x, wr[kk],     accE);
                accO = fmaf(xv.y, wr[kk + 1], accO);
            }
        }
        lg[tg][e] = accE + accO;
        __syncthreads();

        if (tid < 4 && base + tid < nflag) {
            const int t2 = g_flags[base + tid];
            const float* row = lg[tid];
            float v0 = -1e38f, v1 = -1e38f, v2 = -1e38f, v3 = -1e38f, v4 = -1e38f, v5 = -1e38f;
            int   i0 = 0, i1 = 0, i2 = 0, i3 = 0, i4 = 0, i5 = 0;
            for (int k = 0; k < EXPN; k++) {
                float l = row[k];
                if (l > v5) {
                    v5 = l; i5 = k;
                    if (v5 > v4) { float t = v4; v4 = v5; v5 = t; int u = i4; i4 = i5; i5 = u; }
                    if (v4 > v3) { float t = v3; v3 = v4; v4 = t; int u = i3; i3 = i4; i4 = u; }
                    if (v3 > v2) { float t = v2; v2 = v3; v3 = t; int u = i2; i2 = i3; i3 = u; }
                    if (v2 > v1) { float t = v1; v1 = v2; v2 = t; int u = i1; i1 = i2; i2 = u; }
                    if (v1 > v0) { float t = v0; v0 = v1; v1 = t; int u = i0; i0 = i1; i1 = u; }
                }
            }
            float m = v0;
            float ssum = 0.f;
            for (int k = 0; k < EXPN; k++) ssum += expf(row[k] - m);
            float inv = 1.0f / ssum;

            float* out_idx = out;
            float* out_wgt = out + (size_t)BT * TOPK;
            const size_t g = (size_t)t2;
            out_idx[g * TOPK + 0] = (float)i0;
            out_idx[g * TOPK + 1] = (float)i1;
            out_idx[g * TOPK + 2] = (float)i2;
            out_idx[g * TOPK + 3] = (float)i3;
            out_idx[g * TOPK + 4] = (float)i4;
            out_idx[g * TOPK + 5] = (float)i5;
            out_wgt[g * TOPK + 0] = expf(v0 - m) * inv;
            out_wgt[g * TOPK + 1] = expf(v1 - m) * inv;
            out_wgt[g * TOPK + 2] = expf(v2 - m) * inv;
            out_wgt[g * TOPK + 3] = expf(v3 - m) * inv;
            out_wgt[g * TOPK + 4] = expf(v4 - m) * inv;
            out_wgt[g * TOPK + 5] = expf(v5 - m) * inv;
        }
        __syncthreads();
    }

    // merged aux loss (block 0)
    if (blockIdx.x == 0) {
        red[tid] = g_cnts[tid] * g_sums[tid];
        __syncthreads();
#pragma unroll
        for (int s = 128; s > 0; s >>= 1) {
            if (tid < s) red[tid] += red[tid + s];
            __syncthreads();
        }
        if (tid == 0) {
            const float scale = (float)(0.001 * 64.0 / ((double)4 * 4096.0 * 6.0 * 4096.0));
            out[(size_t)BT * 12] = red[0] * scale;
        }
    }
}

extern "C" void kernel_launch(void* const* d_in, const int* in_sizes, int n_in,
                              void* d_out, int out_size) {
    const float* x = (const float*)d_in[0];
    const float* w = (const float*)d_in[1];
    float* out = (float*)d_out;

    cudaFuncSetAttribute(gate_kernel, cudaFuncAttributeMaxDynamicSharedMemorySize, SMEM_BYTES);

    prep_kernel<<<128, 256>>>(w);
    gate_kernel<<<BT / TOKB, NTHR, SMEM_BYTES>>>(x, w, out);
    fixup_kernel<<<128, 256>>>(x, w, out);
}